// round 16
// baseline (speedup 1.0000x reference)
#include <cuda_runtime.h>

// LSTM_40948218200110: B=4096, T=1024, I=8, H=4 (PyTorch gate order) + FC[H->1].
// R14: 8 lanes per element (lane u = p*4+k), 4 elements per warp, 1024 warps.
// EXPLICIT software pipelining: the next step's x-projection (independent packed
// FMAs) is computed between the activation MUFUs and the exchange shuffles, and
// the next step's LDS is issued at the step top — filling the stall windows that
// ptxas won't fill across shfl_sync on its own (the R6 C~254 inflation).
// Exchange: 2 bfly(4) gate-pair swaps + 3 bfly(1,2,3) h broadcasts = 5 shfl/step.
// Packed fma.rn.f32x2 everywhere; sigmoid 0.5-prescale folded into i/f/o rows.

#define T_STEPS 1024
#define I_DIM   8
#define EPB     8             // elements per block (2 warps x 4)
#define BLOCK   64
#define CH_STEPS 8            // timesteps per smem chunk
#define NCHUNK  (T_STEPS / CH_STEPS)   // 128
#define STRIDE4 17            // float4 stride per element region (pad 16->17)

typedef unsigned long long ull;

__device__ __forceinline__ float tanh_fast(float x) {
    float y;
    asm("tanh.approx.f32 %0, %1;" : "=f"(y) : "f"(x));
    return y;
}
__device__ __forceinline__ ull ffma2(ull a, ull b, ull c) {
    ull d;
    asm("fma.rn.f32x2 %0, %1, %2, %3;" : "=l"(d) : "l"(a), "l"(b), "l"(c));
    return d;
}
__device__ __forceinline__ ull pack2(float lo, float hi) {
    ull d;
    asm("mov.b64 %0, {%1, %2};" : "=l"(d) : "f"(lo), "f"(hi));
    return d;
}
__device__ __forceinline__ float hsum2(ull v) {
    float lo, hi;
    asm("mov.b64 {%0, %1}, %2;" : "=f"(lo), "=f"(hi) : "l"(v));
    return lo + hi;
}

__global__ __launch_bounds__(BLOCK) void lstm_kernel(
    const float* __restrict__ x,     // [B, T, I]
    const float* __restrict__ Wih,   // [16, 8]
    const float* __restrict__ Whh,   // [16, 4]
    const float* __restrict__ bih,   // [16]
    const float* __restrict__ bhh,   // [16]
    const float* __restrict__ fcw,   // [1, 4]
    const float* __restrict__ fcb,   // [1]
    float* __restrict__ out,         // [B, 1]
    int B)
{
    __shared__ float4 sm[2][EPB * STRIDE4];

    const int t    = threadIdx.x;
    const int w    = t >> 5;          // warp 0..1 — owns elements w*4..w*4+3
    const int lane = t & 31;
    const int oct  = lane >> 3;       // element within warp, 0..3
    const int u    = lane & 7;        // lane within octet
    const int k    = u & 3;           // hidden unit
    const int p    = u >> 2;          // 0: (i,f) rows, 1: (g,o) rows
    const int eloc = w * 4 + oct;     // local element 0..7
    const int b    = blockIdx.x * EPB + eloc;

    // Rows owned by this thread.
    const int rowA = p ? (8 + k)  : k;        // i or g
    const int rowB = p ? (12 + k) : (4 + k);  // f or o
    const float sA = p ? 1.0f : 0.5f;         // g: tanh (1.0); i: sigmoid prescale
    const float actA_m = p ? 1.0f : 0.5f, actA_b = p ? 0.0f : 0.5f;

    ull wxA[4], wxB[4], whA[2], whB[2], biA, biB;
#pragma unroll
    for (int j = 0; j < 4; j++) {
        wxA[j] = pack2(sA   * Wih[rowA * I_DIM + 2 * j], sA   * Wih[rowA * I_DIM + 2 * j + 1]);
        wxB[j] = pack2(0.5f * Wih[rowB * I_DIM + 2 * j], 0.5f * Wih[rowB * I_DIM + 2 * j + 1]);
    }
    // Recurrent weights permuted so slot m multiplies h_{k^m} (bfly mask m).
    whA[0] = pack2(sA   * Whh[rowA * 4 + (k ^ 0)], sA   * Whh[rowA * 4 + (k ^ 1)]);
    whA[1] = pack2(sA   * Whh[rowA * 4 + (k ^ 2)], sA   * Whh[rowA * 4 + (k ^ 3)]);
    whB[0] = pack2(0.5f * Whh[rowB * 4 + (k ^ 0)], 0.5f * Whh[rowB * 4 + (k ^ 1)]);
    whB[1] = pack2(0.5f * Whh[rowB * 4 + (k ^ 2)], 0.5f * Whh[rowB * 4 + (k ^ 3)]);
    biA = pack2(sA   * (bih[rowA] + bhh[rowA]), 0.0f);
    biB = pack2(0.5f * (bih[rowB] + bhh[rowB]), 0.0f);

    float hs = 0.f, hx1 = 0.f, hx2 = 0.f, hx3 = 0.f;
    float c = 0.f;
    const unsigned FULL = 0xffffffffu;

    // Staging: 128 float4 per chunk (8 elem x 16 quads); 64 threads x 2 each.
    const float4* xf4 = reinterpret_cast<const float4*>(x);
    const int e0 = t >> 4,        q0 = t & 15;
    const int e1 = (t + 64) >> 4, q1 = (t + 64) & 15;
    const size_t g0 = (size_t)(blockIdx.x * EPB + e0) * (T_STEPS * 2) + q0;
    const size_t g1 = (size_t)(blockIdx.x * EPB + e1) * (T_STEPS * 2) + q1;

    // Prologue: stage chunk 0.
    sm[0][e0 * STRIDE4 + q0] = xf4[g0];
    sm[0][e1 * STRIDE4 + q1] = xf4[g1];
    __syncthreads();

    const ulonglong2* xe0 = reinterpret_cast<const ulonglong2*>(&sm[0][eloc * STRIDE4]);
    const ulonglong2* xe1 = reinterpret_cast<const ulonglong2*>(&sm[1][eloc * STRIDE4]);

    for (int ck = 0; ck < NCHUNK; ck++) {
        float4 pf0, pf1;
        const bool more = (ck + 1 < NCHUNK);
        if (more) {
            pf0 = xf4[g0 + (size_t)(ck + 1) * 16];
            pf1 = xf4[g1 + (size_t)(ck + 1) * 16];
        }

        const ulonglong2* xe = (ck & 1) ? xe1 : xe0;

        // ---- step 0 accumulators (chunk-boundary bubble) ----
        ulonglong2 xlo = xe[0], xhi = xe[1];
        ull accA = ffma2(wxA[0], xlo.x, biA);
        accA = ffma2(wxA[1], xlo.y, accA);
        accA = ffma2(wxA[2], xhi.x, accA);
        accA = ffma2(wxA[3], xhi.y, accA);
        ull accB = ffma2(wxB[0], xlo.x, biB);
        accB = ffma2(wxB[1], xlo.y, accB);
        accB = ffma2(wxB[2], xhi.x, accB);
        accB = ffma2(wxB[3], xhi.y, accB);

#pragma unroll
        for (int s = 0; s < CH_STEPS; s++) {
            // issue next step's LDS first (29-cyc latency hides under this step)
            ulonglong2 nxlo, nxhi;
            if (s + 1 < CH_STEPS) { nxlo = xe[2 * s + 2]; nxhi = xe[2 * s + 3]; }

            // finish gates: recurrent terms on top of prebuilt x-accumulators
            const ull h01 = pack2(hs,  hx1);
            const ull h23 = pack2(hx2, hx3);
            ull rA = ffma2(whA[1], h23, accA);
            rA = ffma2(whA[0], h01, rA);
            ull rB = ffma2(whB[1], h23, accB);
            rB = ffma2(whB[0], h01, rB);
            const float za = hsum2(rA);
            const float zb = hsum2(rB);

            // aa: p=0 -> sigmoid(i), p=1 -> tanh(g). ab: sigmoid (f or o).
            const float aa = fmaf(tanh_fast(za), actA_m, actA_b);
            const float ab = fmaf(tanh_fast(zb), 0.5f, 0.5f);

            // ---- filler: next step's x-projection, independent of this step ----
            if (s + 1 < CH_STEPS) {
                ull nA = ffma2(wxA[0], nxlo.x, biA);
                nA = ffma2(wxA[1], nxlo.y, nA);
                nA = ffma2(wxA[2], nxhi.x, nA);
                nA = ffma2(wxA[3], nxhi.y, nA);
                ull nB = ffma2(wxB[0], nxlo.x, biB);
                nB = ffma2(wxB[1], nxlo.y, nB);
                nB = ffma2(wxB[2], nxhi.x, nB);
                nB = ffma2(wxB[3], nxhi.y, nB);
                accA = nA; accB = nB;
            }

            // gate-pair swap between octet halves (parallel bflys)
            const float eA = __shfl_xor_sync(FULL, aa, 4);  // p0 gets g, p1 gets i
            const float eB = __shfl_xor_sync(FULL, ab, 4);  // p0 gets o, p1 gets f

            const float fgate = p ? eB : ab;
            const float ogate = p ? ab : eB;
            c  = fmaf(fgate, c, aa * eA);   // i*g == aa*eA in both halves
            hs = ogate * tanh_fast(c);

            // h broadcast within the quad (parallel bflys)
            hx1 = __shfl_xor_sync(FULL, hs, 1);
            hx2 = __shfl_xor_sync(FULL, hs, 2);
            hx3 = __shfl_xor_sync(FULL, hs, 3);
        }

        if (more) {
            sm[(ck + 1) & 1][e0 * STRIDE4 + q0] = pf0;
            sm[(ck + 1) & 1][e1 * STRIDE4 + q1] = pf1;
        }
        __syncthreads();
    }

    // ---- final FC: lane u==0 (k=0,p=0) holds h0=hs, h1=hx1, h2=hx2, h3=hx3 ----
    if (u == 0) {
        out[b] = fmaf(hs, fcw[0], fmaf(hx1, fcw[1], fmaf(hx2, fcw[2], fmaf(hx3, fcw[3], fcb[0]))));
    }
}

extern "C" void kernel_launch(void* const* d_in, const int* in_sizes, int n_in,
                              void* d_out, int out_size)
{
    const float* x    = (const float*)d_in[0];
    const float* Wih  = (const float*)d_in[1];
    const float* Whh  = (const float*)d_in[2];
    const float* bih  = (const float*)d_in[3];
    const float* bhh  = (const float*)d_in[4];
    const float* fcw  = (const float*)d_in[5];
    const float* fcb  = (const float*)d_in[6];
    float* out = (float*)d_out;

    const int B = in_sizes[0] / (T_STEPS * I_DIM);   // 4096
    const int grid = B / EPB;                        // 512 blocks of 2 warps

    lstm_kernel<<<grid, BLOCK>>>(x, Wih, Whh, bih, bhh, fcw, fcb, out, B);
}

// round 17
// speedup vs baseline: 1.0061x; 1.0061x over previous
#include <cuda_runtime.h>

// LSTM_40948218200110: B=4096, T=1024, I=8, H=4 (PyTorch gate order) + FC[H->1].
// R15: "cloned-quad" 4-lane topology. 8 lanes per element = TWO redundant 4-lane
// quads (clone exists only to double warp count: 1024 warps, W=1.73/SMSP).
// Each lane owns ALL 4 gate rows of its hidden unit k -> no act-gather round;
// the only dependent shuffle round is the 3 parallel h-butterflies (masks 1,2,3).
// Shortest possible chain for H=4 (~102 cyc). Packed fma.rn.f32x2 dot products,
// recurrent weights k^m-permuted, sigmoid 0.5-prescale folded into i/f/o rows.
// x staged via smem double buffer (block-wide sync variant, best measured).

#define T_STEPS 1024
#define I_DIM   8
#define EPB     8             // elements per block (2 warps x 4)
#define BLOCK   64
#define CH_STEPS 8            // timesteps per smem chunk
#define NCHUNK  (T_STEPS / CH_STEPS)   // 128
#define STRIDE4 17            // float4 stride per element region (pad 16->17)

typedef unsigned long long ull;

__device__ __forceinline__ float tanh_fast(float x) {
    float y;
    asm("tanh.approx.f32 %0, %1;" : "=f"(y) : "f"(x));
    return y;
}
__device__ __forceinline__ ull ffma2(ull a, ull b, ull c) {
    ull d;
    asm("fma.rn.f32x2 %0, %1, %2, %3;" : "=l"(d) : "l"(a), "l"(b), "l"(c));
    return d;
}
__device__ __forceinline__ ull pack2(float lo, float hi) {
    ull d;
    asm("mov.b64 %0, {%1, %2};" : "=l"(d) : "f"(lo), "f"(hi));
    return d;
}
__device__ __forceinline__ float hsum2(ull v) {
    float lo, hi;
    asm("mov.b64 {%0, %1}, %2;" : "=f"(lo), "=f"(hi) : "l"(v));
    return lo + hi;
}

__global__ __launch_bounds__(BLOCK) void lstm_kernel(
    const float* __restrict__ x,     // [B, T, I]
    const float* __restrict__ Wih,   // [16, 8]
    const float* __restrict__ Whh,   // [16, 4]
    const float* __restrict__ bih,   // [16]
    const float* __restrict__ bhh,   // [16]
    const float* __restrict__ fcw,   // [1, 4]
    const float* __restrict__ fcb,   // [1]
    float* __restrict__ out,         // [B, 1]
    int B)
{
    __shared__ float4 sm[2][EPB * STRIDE4];

    const int t    = threadIdx.x;
    const int w    = t >> 5;          // warp 0..1
    const int lane = t & 31;
    const int eIW  = lane >> 3;       // element within warp, 0..3
    const int u    = lane & 7;        // lane within octet (two clone quads)
    const int k    = u & 3;           // hidden unit owned by this lane
    const int eloc = w * 4 + eIW;     // local element 0..7
    const int b    = blockIdx.x * EPB + eloc;

    // ---- Packed weights: gate r in {0:i,1:f,2:g,3:o}, row = 4r + k.
    // sigmoid(z)=0.5*tanh(0.5z)+0.5 -> fold 0.5 prescale into i/f/o rows.
    ull wx[4][4], wh[4][2], bia[4];
#pragma unroll
    for (int r = 0; r < 4; r++) {
        const int row = 4 * r + k;
        const float s = (r == 2) ? 1.0f : 0.5f;
#pragma unroll
        for (int j = 0; j < 4; j++)
            wx[r][j] = pack2(s * Wih[row * I_DIM + 2 * j], s * Wih[row * I_DIM + 2 * j + 1]);
        // recurrent weights permuted so slot m multiplies h_{k^m} (bfly mask m)
        wh[r][0] = pack2(s * Whh[row * 4 + (k ^ 0)], s * Whh[row * 4 + (k ^ 1)]);
        wh[r][1] = pack2(s * Whh[row * 4 + (k ^ 2)], s * Whh[row * 4 + (k ^ 3)]);
        bia[r] = pack2(s * (bih[row] + bhh[row]), 0.0f);
    }

    float hs = 0.f, hx1 = 0.f, hx2 = 0.f, hx3 = 0.f;   // h_k, h_{k^1}, h_{k^2}, h_{k^3}
    float c = 0.f;
    const unsigned FULL = 0xffffffffu;

    // ---- Staging: 128 float4 per chunk (8 elem x 16 quads); 64 threads x 2 each.
    const float4* xf4 = reinterpret_cast<const float4*>(x);
    const int e0 = t >> 4,        q0 = t & 15;
    const int e1 = (t + 64) >> 4, q1 = (t + 64) & 15;
    const size_t g0 = (size_t)(blockIdx.x * EPB + e0) * (T_STEPS * 2) + q0;
    const size_t g1 = (size_t)(blockIdx.x * EPB + e1) * (T_STEPS * 2) + q1;

    // Prologue: stage chunk 0.
    sm[0][e0 * STRIDE4 + q0] = xf4[g0];
    sm[0][e1 * STRIDE4 + q1] = xf4[g1];
    __syncthreads();

    const ulonglong2* xe0 = reinterpret_cast<const ulonglong2*>(&sm[0][eloc * STRIDE4]);
    const ulonglong2* xe1 = reinterpret_cast<const ulonglong2*>(&sm[1][eloc * STRIDE4]);

    for (int ck = 0; ck < NCHUNK; ck++) {
        float4 pf0, pf1;
        const bool more = (ck + 1 < NCHUNK);
        if (more) {
            pf0 = xf4[g0 + (size_t)(ck + 1) * 16];
            pf1 = xf4[g1 + (size_t)(ck + 1) * 16];
        }

        const ulonglong2* xe = (ck & 1) ? xe1 : xe0;

#pragma unroll
        for (int sI = 0; sI < CH_STEPS; sI++) {
            const ulonglong2 xlo = xe[2 * sI];       // x0,x1 | x2,x3 (packed pairs)
            const ulonglong2 xhi = xe[2 * sI + 1];   // x4,x5 | x6,x7

            const ull h01 = pack2(hs,  hx1);
            const ull h23 = pack2(hx2, hx3);

            // Four gate rows, all local to this lane (x part off the critical path,
            // recurrent terms last so the chain from h-arrival is 2 ffma2 + hsum).
            float z[4];
#pragma unroll
            for (int r = 0; r < 4; r++) {
                ull acc = ffma2(wx[r][0], xlo.x, bia[r]);
                acc = ffma2(wx[r][1], xlo.y, acc);
                acc = ffma2(wx[r][2], xhi.x, acc);
                acc = ffma2(wx[r][3], xhi.y, acc);
                acc = ffma2(wh[r][0], h01, acc);
                acc = ffma2(wh[r][1], h23, acc);
                z[r] = hsum2(acc);
            }

            // All four activations local — no gather round.
            const float ai = fmaf(tanh_fast(z[0]), 0.5f, 0.5f);
            const float af = fmaf(tanh_fast(z[1]), 0.5f, 0.5f);
            const float ag = tanh_fast(z[2]);
            const float ao = fmaf(tanh_fast(z[3]), 0.5f, 0.5f);

            c  = fmaf(af, c, ai * ag);
            hs = ao * tanh_fast(c);

            // ONE dependent shuffle round: 3 parallel butterflies within the quad.
            hx1 = __shfl_xor_sync(FULL, hs, 1);
            hx2 = __shfl_xor_sync(FULL, hs, 2);
            hx3 = __shfl_xor_sync(FULL, hs, 3);
        }

        if (more) {
            sm[(ck + 1) & 1][e0 * STRIDE4 + q0] = pf0;
            sm[(ck + 1) & 1][e1 * STRIDE4 + q1] = pf1;
        }
        __syncthreads();
    }

    // ---- final FC: lane u==0 of each element holds h0..h3 ----
    if (u == 0) {
        out[b] = fmaf(hs, fcw[0], fmaf(hx1, fcw[1], fmaf(hx2, fcw[2], fmaf(hx3, fcw[3], fcb[0]))));
    }
}

extern "C" void kernel_launch(void* const* d_in, const int* in_sizes, int n_in,
                              void* d_out, int out_size)
{
    const float* x    = (const float*)d_in[0];
    const float* Wih  = (const float*)d_in[1];
    const float* Whh  = (const float*)d_in[2];
    const float* bih  = (const float*)d_in[3];
    const float* bhh  = (const float*)d_in[4];
    const float* fcw  = (const float*)d_in[5];
    const float* fcb  = (const float*)d_in[6];
    float* out = (float*)d_out;

    const int B = in_sizes[0] / (T_STEPS * I_DIM);   // 4096
    const int grid = B / EPB;                        // 512 blocks of 2 warps -> 1024 warps

    lstm_kernel<<<grid, BLOCK>>>(x, Wih, Whh, bih, bhh, fcw, fcb, out, B);
}